// round 8
// baseline (speedup 1.0000x reference)
#include <cuda_runtime.h>
#include <cuda_bf16.h>

// Inputs (metadata order):
//  0: user_embeddings   [500000, 128] f32
//  1: event_embeddings  [100000, 128] f32
//  2: pos_user_idx      [P] i32
//  3: pos_event_idx     [P] i32
//  4: neg_user_idx      [P] i32
//  5: neg_event_idx     [P] i32
//  6: W                 [1, 129] f32
//  7: b                 [1] f32
// Output: [2, P] f32  (pos scores then neg scores)
//
// Strategy: user gathers have ~2.1x index reuse but reuse distance >> L2.
// Bin pairs by user-index high bits so each bin touches a 64MB user slab
// that fits in L2 alongside the 51MB event table; process bins sequentially.
// User DRAM traffic drops from 537MB to ~224MB (unique rows only).

#define EPS 1e-8f
#define NUM_SMS 148
#define BLOCKS_PER_SM 6
#define THREADS 256
#define WARPS_PER_BLOCK (THREADS / 32)

#define NBINS 4
#define BIN_SHIFT 17          // ui >> 17 in [0,3] for ui < 500000
#define CAP (1 << 20)         // per-bin capacity (worst case = all pairs)

// Scratch (static __device__ arrays: allocation-free per harness rules)
__device__ int g_cursor[NBINS];
__device__ int g_u[NBINS * CAP];
__device__ int g_e[NBINS * CAP];
__device__ int g_p[NBINS * CAP];

// ---------------- Phase 0: reset cursors (every graph replay) ----------------
__global__ void init_kernel() {
    if (threadIdx.x < NBINS) g_cursor[threadIdx.x] = 0;
}

// ---------------- Phase 1: scatter pairs into bins ----------------
// Block-aggregated reservation: smem ranks + one global atomicAdd per (block,bin).
__global__ __launch_bounds__(THREADS) void scatter_kernel(
    const int* __restrict__ pu, const int* __restrict__ pe,
    const int* __restrict__ nu, const int* __restrict__ ne,
    int P)
{
    __shared__ int s_cnt[NBINS];
    __shared__ int s_base[NBINS];
    const int total  = 2 * P;
    const int tid    = threadIdx.x;
    const int stride = gridDim.x * blockDim.x;

    for (int base = blockIdx.x * blockDim.x; base < total; base += stride) {
        const int p = base + tid;
        const bool valid = (p < total);

        if (tid < NBINS) s_cnt[tid] = 0;
        __syncthreads();

        int ui = 0, ei = 0, bin = 0, rank = 0;
        if (valid) {
            if (p < P) { ui = __ldg(pu + p);     ei = __ldg(pe + p); }
            else       { ui = __ldg(nu + p - P); ei = __ldg(ne + p - P); }
            bin  = ui >> BIN_SHIFT;
            rank = atomicAdd(&s_cnt[bin], 1);
        }
        __syncthreads();

        if (tid < NBINS) s_base[tid] = atomicAdd(&g_cursor[tid], s_cnt[tid]);
        __syncthreads();

        if (valid) {
            const int pos = bin * CAP + s_base[bin] + rank;
            g_u[pos] = ui;
            g_e[pos] = ei;
            g_p[pos] = p;
        }
        __syncthreads();   // protect s_cnt/s_base reuse next iteration
    }
}

// ---------------- Phase 2: score one bin (user slab L2-resident) ----------------
// 16 lanes per pair, 2 pairs per warp; dense-line coalescing (offsets sub, sub+16).
__global__ __launch_bounds__(THREADS, BLOCKS_PER_SM) void process_bin_kernel(
    const float* __restrict__ users,
    const float* __restrict__ events,
    const float* __restrict__ W,
    const float* __restrict__ bb,
    float*       __restrict__ out,
    int bin)
{
    const int lane = threadIdx.x & 31;
    const int sub  = lane & 15;
    const int grp  = lane >> 4;
    const int wid  = blockIdx.x * WARPS_PER_BLOCK + (threadIdx.x >> 5);
    const int nw   = gridDim.x * WARPS_PER_BLOCK;

    const int count = g_cursor[bin];        // final bin size after scatter
    const int rbase = bin * CAP;

    const float4 w0 = __ldg(reinterpret_cast<const float4*>(W) + sub + 0);
    const float4 w1 = __ldg(reinterpret_cast<const float4*>(W) + sub + 16);
    const float wSim = __ldg(W + 128);
    const float bias = __ldg(bb);

    const float4* u_tab = reinterpret_cast<const float4*>(users);
    const float4* e_tab = reinterpret_cast<const float4*>(events);

    const int n_iters = (count + 1) >> 1;
    for (int i = wid; i < n_iters; i += nw) {
        const int r = i * 2 + grp;
        const bool active = (r < count);

        int ui = 0, ei = 0, p = 0;
        if (active) {
            ui = __ldg(g_u + rbase + r);
            ei = __ldg(g_e + rbase + r);
            p  = __ldg(g_p + rbase + r);
        }

        const float4* urow = u_tab + (size_t)ui * 32 + sub;
        const float4* erow = e_tab + (size_t)ei * 32 + sub;

        // Both tables cached: user slab (64MB) + events (51MB) fit L2 together.
        const float4 u0 = __ldg(urow + 0);
        const float4 u1 = __ldg(urow + 16);
        const float4 e0 = __ldg(erow + 0);
        const float4 e1 = __ldg(erow + 16);

        float ue, uu, ee, uw;
        ue  = u0.x*e0.x + u0.y*e0.y + u0.z*e0.z + u0.w*e0.w;
        ue += u1.x*e1.x + u1.y*e1.y + u1.z*e1.z + u1.w*e1.w;

        uu  = u0.x*u0.x + u0.y*u0.y + u0.z*u0.z + u0.w*u0.w;
        uu += u1.x*u1.x + u1.y*u1.y + u1.z*u1.z + u1.w*u1.w;

        ee  = e0.x*e0.x + e0.y*e0.y + e0.z*e0.z + e0.w*e0.w;
        ee += e1.x*e1.x + e1.y*e1.y + e1.z*e1.z + e1.w*e1.w;

        uw  = u0.x*w0.x + u0.y*w0.y + u0.z*w0.z + u0.w*w0.w;
        uw += u1.x*w1.x + u1.y*w1.y + u1.z*w1.z + u1.w*w1.w;

        #pragma unroll
        for (int off = 8; off > 0; off >>= 1) {
            ue += __shfl_xor_sync(0xffffffffu, ue, off);
            uu += __shfl_xor_sync(0xffffffffu, uu, off);
            ee += __shfl_xor_sync(0xffffffffu, ee, off);
            uw += __shfl_xor_sync(0xffffffffu, uw, off);
        }

        if (sub == 0 && active) {
            const float un  = fmaxf(sqrtf(uu), EPS);
            const float en  = fmaxf(sqrtf(ee), EPS);
            const float sim = ue / (un * en);
            out[p] = fmaf(sim, wSim, uw + bias);
        }
    }
}

extern "C" void kernel_launch(void* const* d_in, const int* in_sizes, int n_in,
                              void* d_out, int out_size)
{
    const float* users  = (const float*)d_in[0];
    const float* events = (const float*)d_in[1];
    const int*   pu     = (const int*)d_in[2];
    const int*   pe     = (const int*)d_in[3];
    const int*   nu     = (const int*)d_in[4];
    const int*   ne     = (const int*)d_in[5];
    const float* W      = (const float*)d_in[6];
    const float* bb     = (const float*)d_in[7];
    float*       out    = (float*)d_out;

    const int P = in_sizes[2];                    // 524288 pairs
    const int blocks = NUM_SMS * BLOCKS_PER_SM;

    init_kernel<<<1, 32>>>();
    scatter_kernel<<<blocks, THREADS>>>(pu, pe, nu, ne, P);
    for (int b = 0; b < NBINS; b++)
        process_bin_kernel<<<blocks, THREADS>>>(users, events, W, bb, out, b);
}